// round 16
// baseline (speedup 1.0000x reference)
#include <cuda_runtime.h>
#include <cuda_bf16.h>

#define N_NODES 100000
#define F_IN 128
#define H 16
#define E_CAP 2000000
#define SCAN_BLOCKS ((N_NODES + 255) / 256)   // 391

// ---------------- device scratch (no allocations allowed) ----------------
__device__ __align__(16) float g_y1 [N_NODES * H];  // x @ W1l
__device__ __align__(16) float g_s1 [N_NODES * H];  // x @ W1r
__device__ __align__(16) float g_y2 [N_NODES * H];  // h1 @ W2l
__device__ __align__(16) float g_s2 [N_NODES * H];  // h1 @ W2r
__device__ __align__(16) unsigned int g_h2bf[N_NODES * 8];  // h2 as bf16x2 words

// CSR scratch (rows placed in arbitrary order; range = [rowptr, rowptr+deg))
__device__ int g_deg   [N_NODES];
__device__ int g_rowptr[N_NODES];
__device__ int g_cursor[N_NODES];
__device__ int g_colidx[E_CAP];
__device__ int g_total;

// index dtype flags: 1 if the corresponding index tensor is int64
__device__ int g_ei64;
__device__ int g_di64;

// packed f32x2 helpers (Blackwell FFMA2 — only reachable via PTX)
#define PACKF2(d, lo, hi) \
    asm("mov.b64 %0, {%1, %2};" : "=l"(d) : "f"(lo), "f"(hi))
#define UNPACKF2(lo, hi, v) \
    asm("mov.b64 {%0, %1}, %2;" : "=f"(lo), "=f"(hi) : "l"(v))
#define FMA2(acc, a, b) \
    asm("fma.rn.f32x2 %0, %1, %2, %0;" : "+l"(acc) : "l"(a), "l"(b))

__device__ __forceinline__ float4 f4add(float4 a, float4 b) {
    return make_float4(a.x + b.x, a.y + b.y, a.z + b.z, a.w + b.w);
}

// ---------------- proj1: y1 = x@W1l, s1 = x@W1r; zero deg/total; probe ---
__global__ void __launch_bounds__(256) k_proj1(const float* __restrict__ x,
                                               const float* __restrict__ W1l,
                                               const float* __restrict__ W1r,
                                               const int* __restrict__ ei32,
                                               const int* __restrict__ di32) {
    __shared__ float wc[F_IN][32];   // [k][f], f in [0,32): L then R
    int t = threadIdx.x;

    if (blockIdx.x == 0 && t == 0) {
        int e64 = 1, d64 = 1;
#pragma unroll
        for (int k = 0; k < 16; k++) {
            if (ei32[2 * k + 1] != 0) e64 = 0;
            if (di32[2 * k + 1] != 0) d64 = 0;
        }
        g_ei64 = e64;
        g_di64 = d64;
        g_total = 0;
    }

    {   // zero degree histogram for this block's nodes
        int node = blockIdx.x * 256 + t;
        if (node < N_NODES) g_deg[node] = 0;
    }

    for (int i = t; i < F_IN * H; i += 256) {
        int k = i >> 4, f = i & 15;
        wc[k][f]      = W1l[i];
        wc[k][f + 16] = W1r[i];
    }
    __syncthreads();

    int fg = t & 3;
    int ng = t >> 2;
    int node0 = (blockIdx.x * 64 + ng) * 4;

    bool v[4];
#pragma unroll
    for (int n = 0; n < 4; n++) v[n] = (node0 + n) < N_NODES;

    unsigned long long acc[4][4];
#pragma unroll
    for (int n = 0; n < 4; n++)
#pragma unroll
        for (int j = 0; j < 4; j++) acc[n][j] = 0ULL;

    const float4* xp = reinterpret_cast<const float4*>(x);

    for (int k4 = 0; k4 < F_IN / 4; k4++) {
        float4 xv[4];
#pragma unroll
        for (int n = 0; n < 4; n++)
            xv[n] = v[n] ? xp[(size_t)(node0 + n) * (F_IN / 4) + k4]
                         : make_float4(0.f, 0.f, 0.f, 0.f);
#pragma unroll
        for (int kk = 0; kk < 4; kk++) {
            const float4 wA = *reinterpret_cast<const float4*>(&wc[k4 * 4 + kk][fg * 8]);
            const float4 wB = *reinterpret_cast<const float4*>(&wc[k4 * 4 + kk][fg * 8 + 4]);
            unsigned long long w01, w23, w45, w67;
            PACKF2(w01, wA.x, wA.y);
            PACKF2(w23, wA.z, wA.w);
            PACKF2(w45, wB.x, wB.y);
            PACKF2(w67, wB.z, wB.w);
#pragma unroll
            for (int n = 0; n < 4; n++) {
                float xs = (kk == 0) ? xv[n].x : (kk == 1) ? xv[n].y
                         : (kk == 2) ? xv[n].z : xv[n].w;
                unsigned long long xs2;
                PACKF2(xs2, xs, xs);
                FMA2(acc[n][0], xs2, w01);
                FMA2(acc[n][1], xs2, w23);
                FMA2(acc[n][2], xs2, w45);
                FMA2(acc[n][3], xs2, w67);
            }
        }
    }

#pragma unroll
    for (int n = 0; n < 4; n++) {
        if (!v[n]) continue;
        int node = node0 + n;
        float a0, a1, a2, a3, a4, a5, a6, a7;
        UNPACKF2(a0, a1, acc[n][0]);
        UNPACKF2(a2, a3, acc[n][1]);
        UNPACKF2(a4, a5, acc[n][2]);
        UNPACKF2(a6, a7, acc[n][3]);
        float* dst = (fg < 2) ? &g_y1[node * H + fg * 8]
                              : &g_s1[node * H + (fg - 2) * 8];
        float4* d4 = reinterpret_cast<float4*>(dst);
        d4[0] = make_float4(a0, a1, a2, a3);
        d4[1] = make_float4(a4, a5, a6, a7);
    }
}

// ---------------- CSR build --------------------------------------------------
__device__ __forceinline__ int load_dst(const void* eiv, int e, int E) {
    if (g_ei64) return (int)((const long long*)eiv)[E + e];
    return ((const int*)eiv)[E + e];
}
__device__ __forceinline__ int load_src(const void* eiv, int e, int E) {
    if (g_ei64) return (int)((const long long*)eiv)[e];
    return ((const int*)eiv)[e];
}

// 4 edges per thread (REDG has no return latency; this just shrinks the grid)
__global__ void __launch_bounds__(256) k_hist(const void* __restrict__ eiv, int E) {
    int base = (blockIdx.x * blockDim.x + threadIdx.x) * 4;
#pragma unroll
    for (int j = 0; j < 4; j++) {
        int e = base + j;
        if (e < E) atomicAdd(&g_deg[load_dst(eiv, e, E)], 1);
    }
}

// One-kernel range allocation: block-local scan + atomic base grab.
// Row ranges land in arbitrary global order (valid: agg uses beg+deg).
__global__ void __launch_bounds__(256) k_alloc() {
    __shared__ int wsum[8];
    __shared__ int sbase;
    int t = threadIdx.x;
    int lane = t & 31, wid = t >> 5;
    int node = blockIdx.x * 256 + t;
    int d = (node < N_NODES) ? g_deg[node] : 0;

    // inclusive warp scan
    int x = d;
#pragma unroll
    for (int off = 1; off < 32; off <<= 1) {
        int v = __shfl_up_sync(0xffffffffu, x, off);
        if (lane >= off) x += v;
    }
    if (lane == 31) wsum[wid] = x;
    __syncthreads();
    if (t == 0) {
        int run = 0;
#pragma unroll
        for (int i = 0; i < 8; i++) { int v = wsum[i]; wsum[i] = run; run += v; }
        sbase = atomicAdd(&g_total, run);
    }
    __syncthreads();
    if (node < N_NODES) {
        int r = sbase + wsum[wid] + (x - d);   // exclusive prefix
        g_rowptr[node] = r;
        g_cursor[node] = r;
    }
}

// 4 edges per thread: 4 independent returning atomics in flight (MLP 1->4).
// The cursor atomicAdd RETURNS a slot; serial per-edge chains were the wall.
__global__ void __launch_bounds__(256) k_fill(const void* __restrict__ eiv, int E) {
    int base = (blockIdx.x * blockDim.x + threadIdx.x) * 4;
    if (base >= E) return;

    int src[4], dst[4], pos[4];
    bool ok[4];
#pragma unroll
    for (int j = 0; j < 4; j++) {
        int e = base + j;
        ok[j] = e < E;
        int ec = ok[j] ? e : E - 1;
        src[j] = load_src(eiv, ec, E);
        dst[j] = load_dst(eiv, ec, E);
    }
#pragma unroll
    for (int j = 0; j < 4; j++)
        if (ok[j]) pos[j] = atomicAdd(&g_cursor[dst[j]], 1);
#pragma unroll
    for (int j = 0; j < 4; j++)
        if (ok[j] && pos[j] < E_CAP) g_colidx[pos[j]] = src[j];
}

// ---------------- agg helper: lane q sums quarter q over CSR neighbors ---
__device__ __forceinline__ float4 agg_quarter(const float* __restrict__ ysrc,
                                              int node, int q) {
    int beg = g_rowptr[node];
    int end = beg + g_deg[node];
    const float4* yp = reinterpret_cast<const float4*>(ysrc);
    float4 a0 = make_float4(0.f, 0.f, 0.f, 0.f);
    float4 a1 = make_float4(0.f, 0.f, 0.f, 0.f);
    int i = beg;
    for (; i + 3 < end; i += 4) {
        int s0 = g_colidx[i],     s1 = g_colidx[i + 1];
        int s2 = g_colidx[i + 2], s3 = g_colidx[i + 3];
        float4 v0 = yp[(size_t)s0 * 4 + q];
        float4 v1 = yp[(size_t)s1 * 4 + q];
        float4 v2 = yp[(size_t)s2 * 4 + q];
        float4 v3 = yp[(size_t)s3 * 4 + q];
        a0 = f4add(a0, v0);
        a1 = f4add(a1, v1);
        a0 = f4add(a0, v2);
        a1 = f4add(a1, v3);
    }
    for (; i < end; i++)
        a0 = f4add(a0, yp[(size_t)g_colidx[i] * 4 + q]);
    return f4add(a0, a1);
}

// ---- fused: agg(y1) -> h1 = relu(mean + b1 + s1) -> y2/s2 = h1@W2{l,r} --
// 4 lanes per node; lane q owns quarter q. h quarters exchanged via shfl.
__global__ void __launch_bounds__(256) k_aggh1(const float* __restrict__ b1,
                                               const float* __restrict__ W2l,
                                               const float* __restrict__ W2r) {
    __shared__ float w2[H][32];   // [k][f]: L then R
    __shared__ float sb1[H];
    int t = threadIdx.x;
    {   // H*H = 256 == blockDim
        int k = t >> 4, f = t & 15;
        w2[k][f]      = W2l[t];
        w2[k][f + 16] = W2r[t];
    }
    if (t < H) sb1[t] = b1[t];
    __syncthreads();

    int gid = blockIdx.x * 256 + t;
    int node = gid >> 2;
    int q = gid & 3;
    if (node >= N_NODES) return;
    unsigned mask = __activemask();
    int gbase = (t & 31) & ~3;

    float4 a = agg_quarter(g_y1, node, q);
    float inv = 1.0f / fmaxf((float)g_deg[node], 1.0f);
    float4 s = reinterpret_cast<const float4*>(g_s1)[(size_t)node * 4 + q];

    float hq[4];
    hq[0] = fmaxf(a.x * inv + sb1[q * 4 + 0] + s.x, 0.0f);
    hq[1] = fmaxf(a.y * inv + sb1[q * 4 + 1] + s.y, 0.0f);
    hq[2] = fmaxf(a.z * inv + sb1[q * 4 + 2] + s.z, 0.0f);
    hq[3] = fmaxf(a.w * inv + sb1[q * 4 + 3] + s.w, 0.0f);

    // exchange quarters within the quad -> full h[16]
    float h[H];
#pragma unroll
    for (int p = 0; p < 4; p++) {
#pragma unroll
        for (int j = 0; j < 4; j++)
            h[p * 4 + j] = __shfl_sync(mask, hq[j], gbase + p);
    }

    // lane q computes y2/s2 quarter q
    float oy[4] = {0.f, 0.f, 0.f, 0.f};
    float os[4] = {0.f, 0.f, 0.f, 0.f};
#pragma unroll
    for (int k = 0; k < H; k++) {
        float hk = h[k];
        float4 wl = *reinterpret_cast<const float4*>(&w2[k][q * 4]);
        float4 wr = *reinterpret_cast<const float4*>(&w2[k][16 + q * 4]);
        oy[0] = fmaf(hk, wl.x, oy[0]);
        oy[1] = fmaf(hk, wl.y, oy[1]);
        oy[2] = fmaf(hk, wl.z, oy[2]);
        oy[3] = fmaf(hk, wl.w, oy[3]);
        os[0] = fmaf(hk, wr.x, os[0]);
        os[1] = fmaf(hk, wr.y, os[1]);
        os[2] = fmaf(hk, wr.z, os[2]);
        os[3] = fmaf(hk, wr.w, os[3]);
    }
    reinterpret_cast<float4*>(g_y2)[(size_t)node * 4 + q] =
        make_float4(oy[0], oy[1], oy[2], oy[3]);
    reinterpret_cast<float4*>(g_s2)[(size_t)node * 4 + q] =
        make_float4(os[0], os[1], os[2], os[3]);
}

// ---- fused: agg(y2) -> h2 = mean + b2 + s2 -> bf16 store ----------------
__global__ void __launch_bounds__(256) k_aggh2(const float* __restrict__ b2) {
    __shared__ float sb2[H];
    int t = threadIdx.x;
    if (t < H) sb2[t] = b2[t];
    __syncthreads();

    int gid = blockIdx.x * 256 + t;
    int node = gid >> 2;
    int q = gid & 3;
    if (node >= N_NODES) return;

    float4 a = agg_quarter(g_y2, node, q);
    float inv = 1.0f / fmaxf((float)g_deg[node], 1.0f);
    float4 s = reinterpret_cast<const float4*>(g_s2)[(size_t)node * 4 + q];

    float h0 = a.x * inv + sb2[q * 4 + 0] + s.x;
    float h1 = a.y * inv + sb2[q * 4 + 1] + s.y;
    float h2 = a.z * inv + sb2[q * 4 + 2] + s.z;
    float h3 = a.w * inv + sb2[q * 4 + 3] + s.w;

    __nv_bfloat162 b01 = __float22bfloat162_rn(make_float2(h0, h1));
    __nv_bfloat162 b23 = __float22bfloat162_rn(make_float2(h2, h3));
    uint2 w;
    w.x = *reinterpret_cast<unsigned int*>(&b01);
    w.y = *reinterpret_cast<unsigned int*>(&b23);
    reinterpret_cast<uint2*>(g_h2bf)[(size_t)node * 4 + q] = w;
}

// ---------------- decode: sigmoid(<h2[i], h2[j]>), 2 threads/pair --------
__global__ void __launch_bounds__(256) k_decode(const void* __restrict__ div,
                                                int P, float* __restrict__ out) {
    int gid = blockIdx.x * blockDim.x + threadIdx.x;
    int p = gid >> 1;
    int s = gid & 1;
    if (p >= P) return;
    unsigned mask = __activemask();

    int idx;
    if (g_di64) {
        const long long* di = (const long long*)div;
        idx = (int)di[(size_t)s * P + p];
    } else {
        const int* di = (const int*)div;
        idx = di[(size_t)s * P + p];
    }

    const uint4* r4 = reinterpret_cast<const uint4*>(g_h2bf + (size_t)idx * 8);
    uint4 u0 = r4[0], u1 = r4[1];
    unsigned int w[8] = {u0.x, u0.y, u0.z, u0.w, u1.x, u1.y, u1.z, u1.w};

    float r[H];
#pragma unroll
    for (int i = 0; i < 8; i++) {
        r[2 * i]     = __uint_as_float(w[i] << 16);
        r[2 * i + 1] = __uint_as_float(w[i] & 0xffff0000u);
    }

    float partial = 0.0f;
#pragma unroll
    for (int f = 0; f < 8; f++) {
        float sendv = s ? r[f] : r[f + 8];
        float other = __shfl_xor_sync(mask, sendv, 1);
        float mine  = s ? r[f + 8] : r[f];
        partial = fmaf(mine, other, partial);
    }
    float total = partial + __shfl_xor_sync(mask, partial, 1);
    if (s == 0) out[p] = 1.0f / (1.0f + __expf(-total));
}

// ---------------- launch ---------------------------------------------------
extern "C" void kernel_launch(void* const* d_in, const int* in_sizes, int n_in,
                              void* d_out, int out_size) {
    const float* x   = (const float*)d_in[0];
    const float* W1l = (const float*)d_in[1];
    const float* b1  = (const float*)d_in[2];
    const float* W1r = (const float*)d_in[3];
    const float* W2l = (const float*)d_in[4];
    const float* b2  = (const float*)d_in[5];
    const float* W2r = (const float*)d_in[6];
    const void*  ei  = d_in[7];
    const void*  di  = d_in[8];
    float* out = (float*)d_out;

    int E = in_sizes[7] / 2;
    int P = in_sizes[8] / 2;
    if (E > E_CAP) E = E_CAP;

    int eblocks4 = (E + 4 * 256 - 1) / (4 * 256);   // 4 edges per thread
    int nblocks4 = (4 * N_NODES + 255) / 256;       // 4 lanes per node

    k_proj1 <<<SCAN_BLOCKS, 256>>>(x, W1l, W1r, (const int*)ei, (const int*)di);
    k_hist  <<<eblocks4, 256>>>(ei, E);
    k_alloc <<<SCAN_BLOCKS, 256>>>();
    k_fill  <<<eblocks4, 256>>>(ei, E);
    k_aggh1 <<<nblocks4, 256>>>(b1, W2l, W2r);
    k_aggh2 <<<nblocks4, 256>>>(b2);
    k_decode<<<(2LL * P + 255) / 256, 256>>>(di, P, out);
}

// round 17
// speedup vs baseline: 1.0062x; 1.0062x over previous
#include <cuda_runtime.h>
#include <cuda_bf16.h>

#define N_NODES 100000
#define F_IN 128
#define H 16
#define E_CAP 2000000
#define SCAN_BLOCKS ((N_NODES + 255) / 256)   // 391
#define PROJ_THREADS (SCAN_BLOCKS * 256)      // 100096

// ---------------- device scratch (no allocations allowed) ----------------
__device__ __align__(16) float g_y1 [N_NODES * H];  // x @ W1l
__device__ __align__(16) float g_s1 [N_NODES * H];  // x @ W1r
__device__ __align__(16) float g_y2 [N_NODES * H];  // h1 @ W2l
__device__ __align__(16) float g_s2 [N_NODES * H];  // h1 @ W2r
__device__ __align__(16) unsigned int g_h2bf[N_NODES * 8];  // h2 as bf16x2 words

// CSR scratch (rows placed in arbitrary order; range = [rowptr, rowptr+deg))
__device__ int g_deg   [N_NODES];
__device__ int g_rowptr[N_NODES];
__device__ int g_cursor[N_NODES];
__device__ int g_colidx[E_CAP];
__device__ int g_total;

// index dtype flags: 1 if the corresponding index tensor is int64
__device__ int g_ei64;
__device__ int g_di64;

// packed f32x2 helpers (Blackwell FFMA2 — only reachable via PTX)
#define PACKF2(d, lo, hi) \
    asm("mov.b64 %0, {%1, %2};" : "=l"(d) : "f"(lo), "f"(hi))
#define UNPACKF2(lo, hi, v) \
    asm("mov.b64 {%0, %1}, %2;" : "=f"(lo), "=f"(hi) : "l"(v))
#define FMA2(acc, a, b) \
    asm("fma.rn.f32x2 %0, %1, %2, %0;" : "+l"(acc) : "l"(a), "l"(b))

__device__ __forceinline__ float4 f4add(float4 a, float4 b) {
    return make_float4(a.x + b.x, a.y + b.y, a.z + b.z, a.w + b.w);
}

// -------- proj1: y1 = x@W1l, s1 = x@W1r; zero deg; probe; FUSED hist -----
// Block: 256 threads, 256 nodes/block. Inner product in packed f32x2.
// The degree histogram (non-returning LSU atomics) is appended at the end:
// chip-wide it overlaps with other warps' FMA work instead of costing its
// own kernel.
__global__ void __launch_bounds__(256) k_proj1(const float* __restrict__ x,
                                               const float* __restrict__ W1l,
                                               const float* __restrict__ W1r,
                                               const void* __restrict__ eiv,
                                               const int* __restrict__ di32,
                                               int E) {
    __shared__ float wc[F_IN][32];   // [k][f], f in [0,32): L then R
    int t = threadIdx.x;
    int gid = blockIdx.x * 256 + t;
    const int* ei32 = (const int*)eiv;

    // per-thread dtype probe for the edge index (needed before fused hist;
    // cannot rely on g_ei64 written by another block in this same kernel).
    int e64 = 1;
#pragma unroll
    for (int k = 0; k < 16; k++)
        if (ei32[2 * k + 1] != 0) e64 = 0;

    if (blockIdx.x == 0 && t == 0) {
        int d64 = 1;
#pragma unroll
        for (int k = 0; k < 16; k++)
            if (di32[2 * k + 1] != 0) d64 = 0;
        g_ei64 = e64;
        g_di64 = d64;
        g_total = 0;
    }

    {   // zero degree histogram for this block's nodes
        int node = gid;
        if (node < N_NODES) g_deg[node] = 0;
    }

    for (int i = t; i < F_IN * H; i += 256) {
        int k = i >> 4, f = i & 15;
        wc[k][f]      = W1l[i];
        wc[k][f + 16] = W1r[i];
    }
    __syncthreads();

    int fg = t & 3;
    int ng = t >> 2;
    int node0 = (blockIdx.x * 64 + ng) * 4;

    bool v[4];
#pragma unroll
    for (int n = 0; n < 4; n++) v[n] = (node0 + n) < N_NODES;

    unsigned long long acc[4][4];
#pragma unroll
    for (int n = 0; n < 4; n++)
#pragma unroll
        for (int j = 0; j < 4; j++) acc[n][j] = 0ULL;

    const float4* xp = reinterpret_cast<const float4*>(x);

    for (int k4 = 0; k4 < F_IN / 4; k4++) {
        float4 xv[4];
#pragma unroll
        for (int n = 0; n < 4; n++)
            xv[n] = v[n] ? xp[(size_t)(node0 + n) * (F_IN / 4) + k4]
                         : make_float4(0.f, 0.f, 0.f, 0.f);
#pragma unroll
        for (int kk = 0; kk < 4; kk++) {
            const float4 wA = *reinterpret_cast<const float4*>(&wc[k4 * 4 + kk][fg * 8]);
            const float4 wB = *reinterpret_cast<const float4*>(&wc[k4 * 4 + kk][fg * 8 + 4]);
            unsigned long long w01, w23, w45, w67;
            PACKF2(w01, wA.x, wA.y);
            PACKF2(w23, wA.z, wA.w);
            PACKF2(w45, wB.x, wB.y);
            PACKF2(w67, wB.z, wB.w);
#pragma unroll
            for (int n = 0; n < 4; n++) {
                float xs = (kk == 0) ? xv[n].x : (kk == 1) ? xv[n].y
                         : (kk == 2) ? xv[n].z : xv[n].w;
                unsigned long long xs2;
                PACKF2(xs2, xs, xs);
                FMA2(acc[n][0], xs2, w01);
                FMA2(acc[n][1], xs2, w23);
                FMA2(acc[n][2], xs2, w45);
                FMA2(acc[n][3], xs2, w67);
            }
        }
    }

#pragma unroll
    for (int n = 0; n < 4; n++) {
        if (!v[n]) continue;
        int node = node0 + n;
        float a0, a1, a2, a3, a4, a5, a6, a7;
        UNPACKF2(a0, a1, acc[n][0]);
        UNPACKF2(a2, a3, acc[n][1]);
        UNPACKF2(a4, a5, acc[n][2]);
        UNPACKF2(a6, a7, acc[n][3]);
        float* dst = (fg < 2) ? &g_y1[node * H + fg * 8]
                              : &g_s1[node * H + (fg - 2) * 8];
        float4* d4 = reinterpret_cast<float4*>(dst);
        d4[0] = make_float4(a0, a1, a2, a3);
        d4[1] = make_float4(a4, a5, a6, a7);
    }

    // ---- fused degree histogram (non-returning atomics; LSU pipe) ----
    if (e64) {
        const long long* ei = (const long long*)eiv;
        for (int e = gid; e < E; e += PROJ_THREADS)
            atomicAdd(&g_deg[(int)ei[E + e]], 1);
    } else {
        for (int e = gid; e < E; e += PROJ_THREADS)
            atomicAdd(&g_deg[ei32[E + e]], 1);
    }
}

// ---------------- CSR build --------------------------------------------------
__device__ __forceinline__ int load_dst(const void* eiv, int e, int E) {
    if (g_ei64) return (int)((const long long*)eiv)[E + e];
    return ((const int*)eiv)[E + e];
}
__device__ __forceinline__ int load_src(const void* eiv, int e, int E) {
    if (g_ei64) return (int)((const long long*)eiv)[e];
    return ((const int*)eiv)[e];
}

// One-kernel range allocation: block-local scan + atomic base grab.
// Row ranges land in arbitrary global order (valid: agg uses beg+deg).
__global__ void __launch_bounds__(256) k_alloc() {
    __shared__ int wsum[8];
    __shared__ int sbase;
    int t = threadIdx.x;
    int lane = t & 31, wid = t >> 5;
    int node = blockIdx.x * 256 + t;
    int d = (node < N_NODES) ? g_deg[node] : 0;

    // inclusive warp scan
    int x = d;
#pragma unroll
    for (int off = 1; off < 32; off <<= 1) {
        int v = __shfl_up_sync(0xffffffffu, x, off);
        if (lane >= off) x += v;
    }
    if (lane == 31) wsum[wid] = x;
    __syncthreads();
    if (t == 0) {
        int run = 0;
#pragma unroll
        for (int i = 0; i < 8; i++) { int v = wsum[i]; wsum[i] = run; run += v; }
        sbase = atomicAdd(&g_total, run);
    }
    __syncthreads();
    if (node < N_NODES) {
        int r = sbase + wsum[wid] + (x - d);   // exclusive prefix
        g_rowptr[node] = r;
        g_cursor[node] = r;
    }
}

// 4 edges per thread. NOTE: bound by returning-atomic throughput (~25us);
// MLP does not help (verified R15->R16); kept simple.
__global__ void __launch_bounds__(256) k_fill(const void* __restrict__ eiv, int E) {
    int base = (blockIdx.x * blockDim.x + threadIdx.x) * 4;
    if (base >= E) return;

    int src[4], dst[4], pos[4];
    bool ok[4];
#pragma unroll
    for (int j = 0; j < 4; j++) {
        int e = base + j;
        ok[j] = e < E;
        int ec = ok[j] ? e : E - 1;
        src[j] = load_src(eiv, ec, E);
        dst[j] = load_dst(eiv, ec, E);
    }
#pragma unroll
    for (int j = 0; j < 4; j++)
        if (ok[j]) pos[j] = atomicAdd(&g_cursor[dst[j]], 1);
#pragma unroll
    for (int j = 0; j < 4; j++)
        if (ok[j] && pos[j] < E_CAP) g_colidx[pos[j]] = src[j];
}

// ---------------- agg helper: lane q sums quarter q over CSR neighbors ---
__device__ __forceinline__ float4 agg_quarter(const float* __restrict__ ysrc,
                                              int node, int q) {
    int beg = g_rowptr[node];
    int end = beg + g_deg[node];
    const float4* yp = reinterpret_cast<const float4*>(ysrc);
    float4 a0 = make_float4(0.f, 0.f, 0.f, 0.f);
    float4 a1 = make_float4(0.f, 0.f, 0.f, 0.f);
    int i = beg;
    for (; i + 3 < end; i += 4) {
        int s0 = g_colidx[i],     s1 = g_colidx[i + 1];
        int s2 = g_colidx[i + 2], s3 = g_colidx[i + 3];
        float4 v0 = yp[(size_t)s0 * 4 + q];
        float4 v1 = yp[(size_t)s1 * 4 + q];
        float4 v2 = yp[(size_t)s2 * 4 + q];
        float4 v3 = yp[(size_t)s3 * 4 + q];
        a0 = f4add(a0, v0);
        a1 = f4add(a1, v1);
        a0 = f4add(a0, v2);
        a1 = f4add(a1, v3);
    }
    for (; i < end; i++)
        a0 = f4add(a0, yp[(size_t)g_colidx[i] * 4 + q]);
    return f4add(a0, a1);
}

// ---- fused: agg(y1) -> h1 = relu(mean + b1 + s1) -> y2/s2 = h1@W2{l,r} --
// 4 lanes per node; lane q owns quarter q. h quarters exchanged via shfl.
__global__ void __launch_bounds__(256) k_aggh1(const float* __restrict__ b1,
                                               const float* __restrict__ W2l,
                                               const float* __restrict__ W2r) {
    __shared__ float w2[H][32];   // [k][f]: L then R
    __shared__ float sb1[H];
    int t = threadIdx.x;
    {   // H*H = 256 == blockDim
        int k = t >> 4, f = t & 15;
        w2[k][f]      = W2l[t];
        w2[k][f + 16] = W2r[t];
    }
    if (t < H) sb1[t] = b1[t];
    __syncthreads();

    int gid = blockIdx.x * 256 + t;
    int node = gid >> 2;
    int q = gid & 3;
    if (node >= N_NODES) return;
    unsigned mask = __activemask();
    int gbase = (t & 31) & ~3;

    float4 a = agg_quarter(g_y1, node, q);
    float inv = 1.0f / fmaxf((float)g_deg[node], 1.0f);
    float4 s = reinterpret_cast<const float4*>(g_s1)[(size_t)node * 4 + q];

    float hq[4];
    hq[0] = fmaxf(a.x * inv + sb1[q * 4 + 0] + s.x, 0.0f);
    hq[1] = fmaxf(a.y * inv + sb1[q * 4 + 1] + s.y, 0.0f);
    hq[2] = fmaxf(a.z * inv + sb1[q * 4 + 2] + s.z, 0.0f);
    hq[3] = fmaxf(a.w * inv + sb1[q * 4 + 3] + s.w, 0.0f);

    // exchange quarters within the quad -> full h[16]
    float h[H];
#pragma unroll
    for (int p = 0; p < 4; p++) {
#pragma unroll
        for (int j = 0; j < 4; j++)
            h[p * 4 + j] = __shfl_sync(mask, hq[j], gbase + p);
    }

    // lane q computes y2/s2 quarter q
    float oy[4] = {0.f, 0.f, 0.f, 0.f};
    float os[4] = {0.f, 0.f, 0.f, 0.f};
#pragma unroll
    for (int k = 0; k < H; k++) {
        float hk = h[k];
        float4 wl = *reinterpret_cast<const float4*>(&w2[k][q * 4]);
        float4 wr = *reinterpret_cast<const float4*>(&w2[k][16 + q * 4]);
        oy[0] = fmaf(hk, wl.x, oy[0]);
        oy[1] = fmaf(hk, wl.y, oy[1]);
        oy[2] = fmaf(hk, wl.z, oy[2]);
        oy[3] = fmaf(hk, wl.w, oy[3]);
        os[0] = fmaf(hk, wr.x, os[0]);
        os[1] = fmaf(hk, wr.y, os[1]);
        os[2] = fmaf(hk, wr.z, os[2]);
        os[3] = fmaf(hk, wr.w, os[3]);
    }
    reinterpret_cast<float4*>(g_y2)[(size_t)node * 4 + q] =
        make_float4(oy[0], oy[1], oy[2], oy[3]);
    reinterpret_cast<float4*>(g_s2)[(size_t)node * 4 + q] =
        make_float4(os[0], os[1], os[2], os[3]);
}

// ---- fused: agg(y2) -> h2 = mean + b2 + s2 -> bf16 store ----------------
__global__ void __launch_bounds__(256) k_aggh2(const float* __restrict__ b2) {
    __shared__ float sb2[H];
    int t = threadIdx.x;
    if (t < H) sb2[t] = b2[t];
    __syncthreads();

    int gid = blockIdx.x * 256 + t;
    int node = gid >> 2;
    int q = gid & 3;
    if (node >= N_NODES) return;

    float4 a = agg_quarter(g_y2, node, q);
    float inv = 1.0f / fmaxf((float)g_deg[node], 1.0f);
    float4 s = reinterpret_cast<const float4*>(g_s2)[(size_t)node * 4 + q];

    float h0 = a.x * inv + sb2[q * 4 + 0] + s.x;
    float h1 = a.y * inv + sb2[q * 4 + 1] + s.y;
    float h2 = a.z * inv + sb2[q * 4 + 2] + s.z;
    float h3 = a.w * inv + sb2[q * 4 + 3] + s.w;

    __nv_bfloat162 b01 = __float22bfloat162_rn(make_float2(h0, h1));
    __nv_bfloat162 b23 = __float22bfloat162_rn(make_float2(h2, h3));
    uint2 w;
    w.x = *reinterpret_cast<unsigned int*>(&b01);
    w.y = *reinterpret_cast<unsigned int*>(&b23);
    reinterpret_cast<uint2*>(g_h2bf)[(size_t)node * 4 + q] = w;
}

// ---------------- decode: sigmoid(<h2[i], h2[j]>), 2 threads/pair --------
__global__ void __launch_bounds__(256) k_decode(const void* __restrict__ div,
                                                int P, float* __restrict__ out) {
    int gid = blockIdx.x * blockDim.x + threadIdx.x;
    int p = gid >> 1;
    int s = gid & 1;
    if (p >= P) return;
    unsigned mask = __activemask();

    int idx;
    if (g_di64) {
        const long long* di = (const long long*)div;
        idx = (int)di[(size_t)s * P + p];
    } else {
        const int* di = (const int*)div;
        idx = di[(size_t)s * P + p];
    }

    const uint4* r4 = reinterpret_cast<const uint4*>(g_h2bf + (size_t)idx * 8);
    uint4 u0 = r4[0], u1 = r4[1];
    unsigned int w[8] = {u0.x, u0.y, u0.z, u0.w, u1.x, u1.y, u1.z, u1.w};

    float r[H];
#pragma unroll
    for (int i = 0; i < 8; i++) {
        r[2 * i]     = __uint_as_float(w[i] << 16);
        r[2 * i + 1] = __uint_as_float(w[i] & 0xffff0000u);
    }

    float partial = 0.0f;
#pragma unroll
    for (int f = 0; f < 8; f++) {
        float sendv = s ? r[f] : r[f + 8];
        float other = __shfl_xor_sync(mask, sendv, 1);
        float mine  = s ? r[f + 8] : r[f];
        partial = fmaf(mine, other, partial);
    }
    float total = partial + __shfl_xor_sync(mask, partial, 1);
    if (s == 0) out[p] = 1.0f / (1.0f + __expf(-total));
}

// ---------------- launch ---------------------------------------------------
extern "C" void kernel_launch(void* const* d_in, const int* in_sizes, int n_in,
                              void* d_out, int out_size) {
    const float* x   = (const float*)d_in[0];
    const float* W1l = (const float*)d_in[1];
    const float* b1  = (const float*)d_in[2];
    const float* W1r = (const float*)d_in[3];
    const float* W2l = (const float*)d_in[4];
    const float* b2  = (const float*)d_in[5];
    const float* W2r = (const float*)d_in[6];
    const void*  ei  = d_in[7];
    const void*  di  = d_in[8];
    float* out = (float*)d_out;

    int E = in_sizes[7] / 2;
    int P = in_sizes[8] / 2;
    if (E > E_CAP) E = E_CAP;

    int eblocks4 = (E + 4 * 256 - 1) / (4 * 256);   // 4 edges per thread
    int nblocks4 = (4 * N_NODES + 255) / 256;       // 4 lanes per node

    k_proj1 <<<SCAN_BLOCKS, 256>>>(x, W1l, W1r, ei, (const int*)di, E);
    k_alloc <<<SCAN_BLOCKS, 256>>>();
    k_fill  <<<eblocks4, 256>>>(ei, E);
    k_aggh1 <<<nblocks4, 256>>>(b1, W2l, W2r);
    k_aggh2 <<<nblocks4, 256>>>(b2);
    k_decode<<<(2LL * P + 255) / 256, 256>>>(di, P, out);
}